// round 3
// baseline (speedup 1.0000x reference)
#include <cuda_runtime.h>
#include <cstdint>

#define NN 100000
#define INF_ 128
#define OUTF 64
#define NE 1600000

// Scratch for support = X @ W  (25.6 MB, static device global per harness rules)
__device__ float g_support[(size_t)NN * OUTF];

// ---------------------------------------------------------------------------
// TF32 helpers (3xTF32 split for fp32-class accuracy on tensor cores)
// ---------------------------------------------------------------------------
__device__ __forceinline__ uint32_t f32_to_tf32(float f) {
    uint32_t r;
    asm("cvt.rna.tf32.f32 %0, %1;" : "=r"(r) : "f"(f));
    return r;
}
__device__ __forceinline__ void split_tf32(float f, uint32_t& hi, uint32_t& lo) {
    hi = f32_to_tf32(f);
    lo = f32_to_tf32(f - __uint_as_float(hi));
}
__device__ __forceinline__ void mma_tf32(float c[4],
                                         uint32_t a0, uint32_t a1, uint32_t a2, uint32_t a3,
                                         uint32_t b0, uint32_t b1) {
    asm volatile(
        "mma.sync.aligned.m16n8k8.row.col.f32.tf32.tf32.f32 "
        "{%0,%1,%2,%3}, {%4,%5,%6,%7}, {%8,%9}, {%0,%1,%2,%3};"
        : "+f"(c[0]), "+f"(c[1]), "+f"(c[2]), "+f"(c[3])
        : "r"(a0), "r"(a1), "r"(a2), "r"(a3), "r"(b0), "r"(b1));
}

// ---------------------------------------------------------------------------
// Kernel 1: support = X @ W (tensor core, 3xTF32) + fused out = bias init.
// BM=64, N=64, K=128 (full). 128 threads = 4 warps, each warp owns 16 rows.
// Per warp: 8 n-tiles (m16n8k8) x 16 k-steps x 3 mma (hi*hi + lo*hi + hi*lo).
// smem: xs[64][132] (pitch 132 -> conflict-free A-frag LDS),
//       ws[128][72] (pitch 72  -> conflict-free B-frag LDS).  70656 B dynamic.
// ---------------------------------------------------------------------------
#define XS_PITCH 132
#define WS_PITCH 72
#define GEMM_SMEM_BYTES (64 * XS_PITCH * 4 + 128 * WS_PITCH * 4)

__global__ __launch_bounds__(128)
void gemm_bias_kernel(const float* __restrict__ x, const float* __restrict__ w,
                      const float* __restrict__ bias, float* __restrict__ out, int n) {
    extern __shared__ float smem[];
    float (*xs)[XS_PITCH] = (float (*)[XS_PITCH])smem;
    float (*ws)[WS_PITCH] = (float (*)[WS_PITCH])(smem + 64 * XS_PITCH);

    const int tid  = threadIdx.x;
    const int brow = blockIdx.x * 64;

    // Fused init: out[brow..brow+63][:] = bias  (1024 float4, 8 per thread)
    {
        const float4* b4 = (const float4*)bias;   // 16 float4s
#pragma unroll
        for (int it = 0; it < 8; it++) {
            int i = tid + it * 128;               // 0..1023
            int r = i >> 4;
            int c = i & 15;
            int grow = brow + r;
            if (grow < n) ((float4*)out)[(size_t)grow * 16 + c] = b4[c];
        }
    }

    // Load W [128,64] -> ws (2048 float4, 16 per thread); scalar STS (pitch 72)
#pragma unroll
    for (int it = 0; it < 16; it++) {
        int i = tid + it * 128;
        int k = i >> 4;
        int c = (i & 15) << 2;
        float4 v = *(const float4*)&w[k * OUTF + c];
        ws[k][c] = v.x; ws[k][c + 1] = v.y; ws[k][c + 2] = v.z; ws[k][c + 3] = v.w;
    }
    // Load X tile [64,128] -> xs (2048 float4, 16 per thread); scalar STS (pitch 132)
#pragma unroll
    for (int it = 0; it < 16; it++) {
        int i = tid + it * 128;
        int r = i >> 5;
        int k = (i & 31) << 2;
        int grow = brow + r;
        float4 v = make_float4(0.f, 0.f, 0.f, 0.f);
        if (grow < n) v = *(const float4*)&x[(size_t)grow * INF_ + k];
        xs[r][k] = v.x; xs[r][k + 1] = v.y; xs[r][k + 2] = v.z; xs[r][k + 3] = v.w;
    }
    __syncthreads();

    const int wp    = tid >> 5;
    const int lane  = tid & 31;
    const int gid   = lane >> 2;   // 0..7
    const int t4    = lane & 3;    // 0..3
    const int mbase = wp * 16;

    float acc[8][4] = {};

#pragma unroll 1
    for (int k0 = 0; k0 < 128; k0 += 8) {
        // A fragment: rows mbase+gid, mbase+gid+8; cols k0+t4, k0+t4+4
        uint32_t ah[4], al[4];
        split_tf32(xs[mbase + gid    ][k0 + t4    ], ah[0], al[0]);
        split_tf32(xs[mbase + gid + 8][k0 + t4    ], ah[1], al[1]);
        split_tf32(xs[mbase + gid    ][k0 + t4 + 4], ah[2], al[2]);
        split_tf32(xs[mbase + gid + 8][k0 + t4 + 4], ah[3], al[3]);

#pragma unroll
        for (int nt = 0; nt < 8; nt++) {
            uint32_t bh0, bl0, bh1, bl1;
            split_tf32(ws[k0 + t4    ][nt * 8 + gid], bh0, bl0);
            split_tf32(ws[k0 + t4 + 4][nt * 8 + gid], bh1, bl1);
            mma_tf32(acc[nt], ah[0], ah[1], ah[2], ah[3], bh0, bh1);  // hi*hi
            mma_tf32(acc[nt], al[0], al[1], al[2], al[3], bh0, bh1);  // lo*hi
            mma_tf32(acc[nt], ah[0], ah[1], ah[2], ah[3], bl0, bl1);  // hi*lo
        }
    }

    // Epilogue: C[gid][2*t4], C[gid][2*t4+1], C[gid+8][...]
#pragma unroll
    for (int nt = 0; nt < 8; nt++) {
        int col = nt * 8 + 2 * t4;
        int r0 = brow + mbase + gid;
        if (r0 < n)
            *(float2*)&g_support[(size_t)r0 * OUTF + col] = make_float2(acc[nt][0], acc[nt][1]);
        int r1 = r0 + 8;
        if (r1 < n)
            *(float2*)&g_support[(size_t)r1 * OUTF + col] = make_float2(acc[nt][2], acc[nt][3]);
    }
}

// ---------------------------------------------------------------------------
// Kernel 2: COO scatter.  16 threads per edge: each lane handles one float4.
// Gather = LDG.128, scatter = red.global.add.v4.f32. Both L2-resident.
// ---------------------------------------------------------------------------
__global__ __launch_bounds__(256)
void scatter_kernel(const int* __restrict__ erow, const int* __restrict__ ecol,
                    const float* __restrict__ evals, float* __restrict__ out) {
    long long gid = (long long)blockIdx.x * blockDim.x + threadIdx.x;
    int e = (int)(gid >> 4);
    if (e >= NE) return;
    int f = ((int)gid & 15) << 2;     // 0,4,...,60

    int c = __ldg(&ecol[e]);
    int r = __ldg(&erow[e]);
    float v = __ldg(&evals[e]);

    float4 s = __ldg((const float4*)&g_support[(size_t)c * OUTF + f]);
    float4 g = make_float4(s.x * v, s.y * v, s.z * v, s.w * v);

    float* dst = &out[(size_t)r * OUTF + f];
    asm volatile("red.global.add.v4.f32 [%0], {%1, %2, %3, %4};"
                 :: "l"(dst), "f"(g.x), "f"(g.y), "f"(g.z), "f"(g.w)
                 : "memory");
}

// ---------------------------------------------------------------------------
extern "C" void kernel_launch(void* const* d_in, const int* in_sizes, int n_in,
                              void* d_out, int out_size) {
    const float* x     = (const float*)d_in[0];   // [100000,128]
    const float* w     = (const float*)d_in[1];   // [128,64]
    const float* bias  = (const float*)d_in[2];   // [64]
    const int*   erow  = (const int*)  d_in[3];   // [1.6M]
    const int*   ecol  = (const int*)  d_in[4];   // [1.6M]
    const float* evals = (const float*)d_in[5];   // [1.6M]
    float* out = (float*)d_out;                   // [100000,64]

    const int n = in_sizes[0] / INF_;             // 100000

    // support = X @ W (tensor core) + fused out = bias
    {
        cudaFuncSetAttribute(gemm_bias_kernel,
                             cudaFuncAttributeMaxDynamicSharedMemorySize,
                             GEMM_SMEM_BYTES);
        int blocks = (n + 63) / 64;
        gemm_bias_kernel<<<blocks, 128, GEMM_SMEM_BYTES>>>(x, w, bias, out, n);
    }
    // out += segment_sum(support[ecol] * evals, erow)
    {
        long long threads = (long long)NE * 16;
        int blocks = (int)((threads + 255) / 256);
        scatter_kernel<<<blocks, 256>>>(erow, ecol, evals, out);
    }
}

// round 6
// speedup vs baseline: 1.3462x; 1.3462x over previous
#include <cuda_runtime.h>
#include <cstdint>

#define NN 100000
#define INF_ 128
#define OUTF 64
#define NE 1600000
#define NCHUNK ((NN + 511) / 512)   // 196

// Static device scratch (allocation-free per harness rules)
__device__ float g_support[(size_t)NN * OUTF];   // 25.6 MB
__device__ int   g_counts[NN];
__device__ int   g_rowstart[NN];
__device__ int   g_cursor[NN];
__device__ int   g_chunksum[NCHUNK];
__device__ int2  g_packed[NE];                   // 12.8 MB (col, val-bits) grouped by row

// ---------------------------------------------------------------------------
// Build phase: counting sort of edges by destination row
// ---------------------------------------------------------------------------
__global__ void zero_counts_kernel() {
    int i = blockIdx.x * blockDim.x + threadIdx.x;
    if (i < NN) g_counts[i] = 0;
}

__global__ void hist_kernel(const int* __restrict__ erow) {
    int e = blockIdx.x * blockDim.x + threadIdx.x;
    if (e < NE) atomicAdd(&g_counts[__ldg(&erow[e])], 1);
}

// S1: per-chunk (512) reduction of counts -> g_chunksum[b]
__global__ __launch_bounds__(512)
void scan1_kernel() {
    __shared__ int s[512];
    int t = threadIdx.x, b = blockIdx.x;
    int i = b * 512 + t;
    s[t] = (i < NN) ? g_counts[i] : 0;
    __syncthreads();
#pragma unroll
    for (int off = 256; off > 0; off >>= 1) {
        if (t < off) s[t] += s[t + off];
        __syncthreads();
    }
    if (t == 0) g_chunksum[b] = s[0];
}

// S2: exclusive scan of chunk sums (196 values, one block)
__global__ __launch_bounds__(256)
void scan2_kernel() {
    __shared__ int s[256];
    int t = threadIdx.x;
    int v = (t < NCHUNK) ? g_chunksum[t] : 0;
    s[t] = v;
    __syncthreads();
#pragma unroll
    for (int off = 1; off < 256; off <<= 1) {
        int a = (t >= off) ? s[t - off] : 0;
        __syncthreads();
        s[t] += a;
        __syncthreads();
    }
    if (t < NCHUNK) g_chunksum[t] = s[t] - v;   // exclusive
}

// S3: per-chunk exclusive scan + chunk base -> rowstart & cursor
__global__ __launch_bounds__(512)
void scan3_kernel() {
    __shared__ int s[512];
    int t = threadIdx.x, b = blockIdx.x;
    int i = b * 512 + t;
    int v = (i < NN) ? g_counts[i] : 0;
    s[t] = v;
    __syncthreads();
#pragma unroll
    for (int off = 1; off < 512; off <<= 1) {
        int a = (t >= off) ? s[t - off] : 0;
        __syncthreads();
        s[t] += a;
        __syncthreads();
    }
    if (i < NN) {
        int excl = s[t] - v + g_chunksum[b];
        g_rowstart[i] = excl;
        g_cursor[i]   = excl;
    }
}

__global__ void fill_kernel(const int* __restrict__ erow, const int* __restrict__ ecol,
                            const float* __restrict__ evals) {
    int e = blockIdx.x * blockDim.x + threadIdx.x;
    if (e < NE) {
        int r = __ldg(&erow[e]);
        int pos = atomicAdd(&g_cursor[r], 1);
        g_packed[pos] = make_int2(__ldg(&ecol[e]), __float_as_int(__ldg(&evals[e])));
    }
}

// ---------------------------------------------------------------------------
// support = X @ W.  Tiled fp32 SIMT GEMM (round-2 proven version).
// ---------------------------------------------------------------------------
__global__ __launch_bounds__(256, 2)
void gemm_kernel(const float* __restrict__ x, const float* __restrict__ w, int n) {
    __shared__ float xs[64][132];
    __shared__ float ws[128][68];

    const int tid  = threadIdx.x;
    const int brow = blockIdx.x * 64;

#pragma unroll
    for (int it = 0; it < 8; it++) {
        int i = tid + it * 256;
        int k = i >> 4;
        int c = (i & 15) << 2;
        float4 v = *(const float4*)&w[k * OUTF + c];
        *(float4*)&ws[k][c] = v;
    }
#pragma unroll
    for (int it = 0; it < 8; it++) {
        int i = tid + it * 256;
        int r = i >> 5;
        int k = (i & 31) << 2;
        int grow = brow + r;
        float4 v = make_float4(0.f, 0.f, 0.f, 0.f);
        if (grow < n) v = *(const float4*)&x[(size_t)grow * INF_ + k];
        *(float4*)&xs[r][k] = v;
    }
    __syncthreads();

    const int r0 = (tid >> 4) << 2;
    const int c0 = (tid & 15) << 2;

    float acc[4][4] = {};
#pragma unroll 4
    for (int k = 0; k < 128; k++) {
        float a0 = xs[r0 + 0][k];
        float a1 = xs[r0 + 1][k];
        float a2 = xs[r0 + 2][k];
        float a3 = xs[r0 + 3][k];
        float4 b = *(float4*)&ws[k][c0];
        acc[0][0] += a0 * b.x; acc[0][1] += a0 * b.y; acc[0][2] += a0 * b.z; acc[0][3] += a0 * b.w;
        acc[1][0] += a1 * b.x; acc[1][1] += a1 * b.y; acc[1][2] += a1 * b.z; acc[1][3] += a1 * b.w;
        acc[2][0] += a2 * b.x; acc[2][1] += a2 * b.y; acc[2][2] += a2 * b.z; acc[2][3] += a2 * b.w;
        acc[3][0] += a3 * b.x; acc[3][1] += a3 * b.y; acc[3][2] += a3 * b.z; acc[3][3] += a3 * b.w;
    }

#pragma unroll
    for (int i = 0; i < 4; i++) {
        int grow = brow + r0 + i;
        if (grow < n) {
            float4 v = make_float4(acc[i][0], acc[i][1], acc[i][2], acc[i][3]);
            *(float4*)&g_support[(size_t)grow * OUTF + c0] = v;
        }
    }
}

// ---------------------------------------------------------------------------
// Pull phase: one warp per destination row. Lanes cooperatively load the
// row's (col,val) list, shfl-broadcast, gather float2 per lane from support,
// accumulate in registers, single plain store (no atomics). bias fused.
// ---------------------------------------------------------------------------
__global__ __launch_bounds__(256)
void pull_kernel(const float* __restrict__ bias, float* __restrict__ out) {
    int wid_g = (blockIdx.x * 256 + threadIdx.x) >> 5;
    int lane  = threadIdx.x & 31;
    if (wid_g >= NN) return;

    const int row   = wid_g;
    const int start = g_rowstart[row];
    const int len   = g_counts[row];
    const int2* __restrict__ plist = g_packed + start;

    float2 acc = *(const float2*)&bias[lane * 2];

    for (int base = 0; base < len; base += 32) {
        int rem = len - base;
        int m   = rem < 32 ? rem : 32;
        int2 p = make_int2(0, 0);
        if (lane < m) p = plist[base + lane];

        int j = 0;
        // MLP=4: four independent gathers in flight
        for (; j + 4 <= m; j += 4) {
            int   c0 = __shfl_sync(0xffffffffu, p.x, j + 0);
            float v0 = __int_as_float(__shfl_sync(0xffffffffu, p.y, j + 0));
            int   c1 = __shfl_sync(0xffffffffu, p.x, j + 1);
            float v1 = __int_as_float(__shfl_sync(0xffffffffu, p.y, j + 1));
            int   c2 = __shfl_sync(0xffffffffu, p.x, j + 2);
            float v2 = __int_as_float(__shfl_sync(0xffffffffu, p.y, j + 2));
            int   c3 = __shfl_sync(0xffffffffu, p.x, j + 3);
            float v3 = __int_as_float(__shfl_sync(0xffffffffu, p.y, j + 3));

            float2 s0 = *(const float2*)&g_support[(size_t)c0 * OUTF + lane * 2];
            float2 s1 = *(const float2*)&g_support[(size_t)c1 * OUTF + lane * 2];
            float2 s2 = *(const float2*)&g_support[(size_t)c2 * OUTF + lane * 2];
            float2 s3 = *(const float2*)&g_support[(size_t)c3 * OUTF + lane * 2];

            acc.x += s0.x * v0; acc.y += s0.y * v0;
            acc.x += s1.x * v1; acc.y += s1.y * v1;
            acc.x += s2.x * v2; acc.y += s2.y * v2;
            acc.x += s3.x * v3; acc.y += s3.y * v3;
        }
        for (; j < m; j++) {
            int   c = __shfl_sync(0xffffffffu, p.x, j);
            float v = __int_as_float(__shfl_sync(0xffffffffu, p.y, j));
            float2 s = *(const float2*)&g_support[(size_t)c * OUTF + lane * 2];
            acc.x += s.x * v; acc.y += s.y * v;
        }
    }

    *(float2*)&out[(size_t)row * OUTF + lane * 2] = acc;
}

// ---------------------------------------------------------------------------
extern "C" void kernel_launch(void* const* d_in, const int* in_sizes, int n_in,
                              void* d_out, int out_size) {
    const float* x     = (const float*)d_in[0];   // [100000,128]
    const float* w     = (const float*)d_in[1];   // [128,64]
    const float* bias  = (const float*)d_in[2];   // [64]
    const int*   erow  = (const int*)  d_in[3];   // [1.6M]
    const int*   ecol  = (const int*)  d_in[4];   // [1.6M]
    const float* evals = (const float*)d_in[5];   // [1.6M]
    float* out = (float*)d_out;                   // [100000,64]

    const int n = in_sizes[0] / INF_;             // 100000

    // support = X @ W (SIMT fp32)
    gemm_kernel<<<(n + 63) / 64, 256>>>(x, w, n);

    // Counting sort of edges by destination row
    zero_counts_kernel<<<(NN + 255) / 256, 256>>>();
    hist_kernel<<<(NE + 255) / 256, 256>>>(erow);
    scan1_kernel<<<NCHUNK, 512>>>();
    scan2_kernel<<<1, 256>>>();
    scan3_kernel<<<NCHUNK, 512>>>();
    fill_kernel<<<(NE + 255) / 256, 256>>>(erow, ecol, evals);

    // Pull: out[row] = bias + sum(support[col] * val)
    {
        long long threads = (long long)NN * 32;
        int blocks = (int)((threads + 255) / 256);
        pull_kernel<<<blocks, 256>>>(bias, out);
    }
}